// round 11
// baseline (speedup 1.0000x reference)
#include <cuda_runtime.h>

// ---------------------------------------------------------------------------
// RadarSecondStageGenerator. R11 = R9 two-kernel split + kernel-A halo fix:
// A staged its input with halo-2 offsets while computing with halo-1 indexing
// (one-pixel shift of every tap). A now stages 18x36 at offset -1.
//   A: x = conv3x3(in24 -> 8)  -> g_x
//   B: i2h = conv3x3(x -> 24) + gates + conv1x1(8 -> 12)
// ---------------------------------------------------------------------------

#define THREADS 256
#define TX 32
#define TY 16

typedef unsigned long long u64;

__device__ float g_x[32 * 8 * 128 * 128];   // x scratch (16.7 MB)

__device__ __forceinline__ float sigmoidf_(float x) {
    return __fdividef(1.0f, 1.0f + __expf(-x));
}
__device__ __forceinline__ u64 pk2(float lo, float hi) {
    u64 r; asm("mov.b64 %0, {%1, %2};" : "=l"(r) : "f"(lo), "f"(hi)); return r;
}
__device__ __forceinline__ u64 ffma2(u64 a, u64 b, u64 c) {
    u64 d; asm("fma.rn.f32x2 %0, %1, %2, %3;" : "=l"(d) : "l"(a), "l"(b), "l"(c)); return d;
}
__device__ __forceinline__ float2 upk2(u64 v) {
    float2 f; asm("mov.b64 {%0, %1}, %2;" : "=f"(f.x), "=f"(f.y) : "l"(v)); return f;
}

// ===================== Kernel A: conv3x3 24 -> 8 ===========================
// smem: in [24][18][36] + wcin 1728 + bcin 8 = ~68 KB -> 3 CTAs/SM
#define A_IN_OFF   0
#define A_IN_SIZE  (24*18*36)
#define A_W_OFF    (A_IN_OFF + A_IN_SIZE)
#define A_B_OFF    (A_W_OFF + 1728)
#define A_SMEM_FLOATS (A_B_OFF + 8)
#define A_SMEM_BYTES  (A_SMEM_FLOATS * 4)

__global__ void __launch_bounds__(THREADS, 3)
convA_kernel(const float* __restrict__ radar,
             const float* __restrict__ pred,
             const float* __restrict__ w_cin,
             const float* __restrict__ b_cin)
{
    extern __shared__ float sm[];
    float* in_s   = sm + A_IN_OFF;
    float* wcin_s = sm + A_W_OFF;
    float* bcin_s = sm + A_B_OFF;

    const int tid = threadIdx.x;
    const int b   = blockIdx.z;
    const int ty0 = blockIdx.y * TY;
    const int tx0 = blockIdx.x * TX;

    // weights: wcin_s[((ci*3+ky)*3+kx)*8 + co] = w_cin[((co*24+ci)*3+ky)*3+kx]
    for (int i = tid; i < 1728; i += THREADS) {
        int co = i & 7;
        int r  = i >> 3;
        int ci = r / 9;
        int k  = r - ci * 9;
        wcin_s[i] = w_cin[(co * 24 + ci) * 9 + k];
    }
    if (tid < 8) bcin_s[tid] = b_cin[tid];

    // input tile load, HALO-1: in_s[yy][xx] <- input[ty0+yy-1][tx0+xx-1]
    {
        const int ltx = tid % 36;
        const int lty = tid / 36;
        if (lty < 7) {
            const int gx = tx0 + ltx - 1;
            const bool vx = (unsigned)gx < 128u;
            #pragma unroll 1
            for (int ch = 0; ch < 24; ch++) {
                const float* base = (ch < 12)
                    ? radar + (((b * 12 + ch) << 14))
                    : pred  + (((b * 12 + ch - 12) << 14));
                #pragma unroll
                for (int yy = lty; yy < 18; yy += 7) {
                    const int gy = ty0 + yy - 1;
                    float v = 0.0f;
                    if (vx && (unsigned)gy < 128u)
                        v = __ldg(&base[(gy << 7) + gx]);
                    in_s[(ch * 18 + yy) * 36 + ltx] = v;
                }
            }
        }
    }
    __syncthreads();

    // compute: 2-px strips, 16 rows x 16 strips = 256 threads
    // output (row, xs+px); input rows row+dy (gy-1..gy+1), cols xs+px+dx
    const int row = tid >> 4;
    const int xs  = (tid & 15) * 2;

    u64 acc2[4][2];                         // [co_pair][px]
    #pragma unroll
    for (int cp = 0; cp < 4; cp++) {
        u64 bv = pk2(bcin_s[2 * cp], bcin_s[2 * cp + 1]);
        acc2[cp][0] = bv; acc2[cp][1] = bv;
    }

    #pragma unroll 1
    for (int ci = 0; ci < 24; ci++) {
        #pragma unroll
        for (int dy = 0; dy < 3; dy++) {
            const float* ap = &in_s[(ci * 18 + row + dy) * 36 + xs];
            float2 a01 = *(const float2*)ap;        // xs even -> 8B aligned
            float2 a23 = *(const float2*)(ap + 2);
            u64 ad[4];
            ad[0] = pk2(a01.x, a01.x); ad[1] = pk2(a01.y, a01.y);
            ad[2] = pk2(a23.x, a23.x); ad[3] = pk2(a23.y, a23.y);
            #pragma unroll
            for (int dx = 0; dx < 3; dx++) {
                const u64* wp2 = (const u64*)&wcin_s[((ci * 3 + dy) * 3 + dx) * 8];
                ulonglong2 wA = *(const ulonglong2*)(wp2);
                ulonglong2 wB = *(const ulonglong2*)(wp2 + 2);
                u64 wv[4] = {wA.x, wA.y, wB.x, wB.y};
                #pragma unroll
                for (int cp = 0; cp < 4; cp++) {
                    acc2[cp][0] = ffma2(ad[dx + 0], wv[cp], acc2[cp][0]);
                    acc2[cp][1] = ffma2(ad[dx + 1], wv[cp], acc2[cp][1]);
                }
            }
        }
    }

    // store x (real pixels only)
    const int gy  = ty0 + row;
    const int gx0 = tx0 + xs;
    float* xp = g_x + ((b * 8) << 14) + (gy << 7) + gx0;
    #pragma unroll
    for (int cp = 0; cp < 4; cp++) {
        float2 v0 = upk2(acc2[cp][0]);      // (co=2cp, co=2cp+1) at px 0
        float2 v1 = upk2(acc2[cp][1]);      // at px 1
        *(float2*)(xp + ((2 * cp + 0) << 14)) = make_float2(v0.x, v1.x);
        *(float2*)(xp + ((2 * cp + 1) << 14)) = make_float2(v0.y, v1.y);
    }
}

// ============ Kernel B: conv3x3 8 -> 24 + gates + conv1x1 8 -> 12 ==========
// smem: x [8][18][36] + wi2h 1728 + wout 96 + biases = 28.3 KB
#define B_X_OFF    0
#define B_X_SIZE   (8*18*36)
#define B_W_OFF    (B_X_OFF + B_X_SIZE)
#define B_WO_OFF   (B_W_OFF + 1728)
#define B_BI_OFF   (B_WO_OFF + 96)
#define B_BR_OFF   (B_BI_OFF + 24)
#define B_BO_OFF   (B_BR_OFF + 24)
#define B_SMEM_FLOATS (B_BO_OFF + 12)
#define B_SMEM_BYTES  (B_SMEM_FLOATS * 4)

__global__ void __launch_bounds__(THREADS, 3)
convB_kernel(const float* __restrict__ w_i2h,
             const float* __restrict__ b_i2h,
             const float* __restrict__ b_ret,
             const float* __restrict__ w_out,
             const float* __restrict__ b_out,
             float* __restrict__ out)
{
    extern __shared__ float sm[];
    float* x_s    = sm + B_X_OFF;
    float* wi2h_s = sm + B_W_OFF;
    float* wout_s = sm + B_WO_OFF;
    float* bi2h_s = sm + B_BI_OFF;
    float* bret_s = sm + B_BR_OFF;
    float* bout_s = sm + B_BO_OFF;

    const int tid = threadIdx.x;
    const int b   = blockIdx.z;
    const int ty0 = blockIdx.y * TY;
    const int tx0 = blockIdx.x * TX;

    // weights: wi2h_s[(ci*9 + k)*24 + o] = w_i2h[(o*8+ci)*9+k]
    for (int i = tid; i < 1728; i += THREADS) {
        int o  = i % 24;
        int r  = i / 24;
        int ci = r / 9;
        int k  = r - ci * 9;
        wi2h_s[i] = w_i2h[(o * 8 + ci) * 9 + k];
    }
    if (tid < 96) wout_s[tid] = w_out[tid];
    if (tid < 24) bi2h_s[tid] = b_i2h[tid];
    if (tid < 24) bret_s[tid] = b_ret[tid];
    if (tid < 12) bout_s[tid] = b_out[tid];

    // x tile load with halo1 + zero pad
    {
        const int ltx = tid % 36;
        const int lty = tid / 36;
        if (lty < 7) {
            const int gx = tx0 + ltx - 1;
            const bool vx = (unsigned)gx < 128u;
            #pragma unroll 1
            for (int c = 0; c < 8; c++) {
                const float* base = g_x + (((b * 8 + c) << 14));
                #pragma unroll
                for (int yy = lty; yy < 18; yy += 7) {
                    const int gy = ty0 + yy - 1;
                    float v = 0.0f;
                    if (vx && (unsigned)gy < 128u)
                        v = base[(gy << 7) + gx];
                    x_s[(c * 18 + yy) * 36 + ltx] = v;
                }
            }
        }
    }
    __syncthreads();

    // compute: 2-px strips, 16 rows x 16 strips = 256 threads
    const int prow = tid >> 4;
    const int pxs  = (tid & 15) * 2;

    u64 acc3[12][2];                        // [o_pair][px]
    #pragma unroll
    for (int op = 0; op < 12; op++) {
        u64 bv = pk2(bi2h_s[2 * op], bi2h_s[2 * op + 1]);
        acc3[op][0] = bv; acc3[op][1] = bv;
    }

    #pragma unroll 1
    for (int ci = 0; ci < 8; ci++) {
        #pragma unroll
        for (int dy = 0; dy < 3; dy++) {
            const float* ap = &x_s[(ci * 18 + prow + dy) * 36 + pxs];
            float2 a01 = *(const float2*)ap;
            float2 a23 = *(const float2*)(ap + 2);
            u64 ad[4];
            ad[0] = pk2(a01.x, a01.x); ad[1] = pk2(a01.y, a01.y);
            ad[2] = pk2(a23.x, a23.x); ad[3] = pk2(a23.y, a23.y);
            #pragma unroll
            for (int dx = 0; dx < 3; dx++) {
                const u64* wp2 = (const u64*)&wi2h_s[(ci * 9 + dy * 3 + dx) * 24];
                #pragma unroll
                for (int q = 0; q < 6; q++) {
                    ulonglong2 w2 = *(const ulonglong2*)(wp2 + q * 2);
                    acc3[2 * q + 0][0] = ffma2(ad[dx + 0], w2.x, acc3[2 * q + 0][0]);
                    acc3[2 * q + 0][1] = ffma2(ad[dx + 1], w2.x, acc3[2 * q + 0][1]);
                    acc3[2 * q + 1][0] = ffma2(ad[dx + 0], w2.y, acc3[2 * q + 1][0]);
                    acc3[2 * q + 1][1] = ffma2(ad[dx + 1], w2.y, acc3[2 * q + 1][1]);
                }
            }
        }
    }

    // gates (h2h from h0==0 is just b_ret broadcast)
    float h[8][2];
    #pragma unroll
    for (int cp = 0; cp < 4; cp++) {
        float br0 = bret_s[2 * cp],      br1 = bret_s[2 * cp + 1];
        float bu0 = bret_s[8 + 2 * cp],  bu1 = bret_s[8 + 2 * cp + 1];
        float bm0 = bret_s[16 + 2 * cp], bm1 = bret_s[16 + 2 * cp + 1];
        #pragma unroll
        for (int px = 0; px < 2; px++) {
            float2 ir = upk2(acc3[cp][px]);
            float2 iu = upk2(acc3[4 + cp][px]);
            float2 im = upk2(acc3[8 + cp][px]);
            float rg0 = sigmoidf_(ir.x + br0);
            float rg1 = sigmoidf_(ir.y + br1);
            float ug0 = sigmoidf_(iu.x + bu0);
            float ug1 = sigmoidf_(iu.y + bu1);
            float m0 = fmaf(rg0, bm0, im.x);
            float m1 = fmaf(rg1, bm1, im.y);
            m0 = (m0 >= 0.0f) ? m0 : 0.2f * m0;
            m1 = (m1 >= 0.0f) ? m1 : 0.2f * m1;
            h[2 * cp + 0][px] = (1.0f - ug0) * m0;
            h[2 * cp + 1][px] = (1.0f - ug1) * m1;
        }
    }

    // conv1x1 (8 -> 12) + store
    const int gy  = ty0 + prow;
    const int gx0 = tx0 + pxs;
    float* op_ = out + ((b * 12) << 14) + (gy << 7) + gx0;
    u64 hp[8];
    #pragma unroll
    for (int c = 0; c < 8; c++) hp[c] = pk2(h[c][0], h[c][1]);
    #pragma unroll
    for (int t = 0; t < 12; t++) {
        u64 o01 = pk2(bout_s[t], bout_s[t]);
        #pragma unroll
        for (int c = 0; c < 8; c++) {
            float w = wout_s[t * 8 + c];
            o01 = ffma2(hp[c], pk2(w, w), o01);
        }
        float2 a = upk2(o01);
        *(float2*)(op_ + (t << 14)) = a;
    }
}

extern "C" void kernel_launch(void* const* d_in, const int* in_sizes, int n_in,
                              void* d_out, int out_size)
{
    const float* radar = (const float*)d_in[0];   // (32,12,1,128,128)
    const float* pred  = (const float*)d_in[1];   // (32,12,1,128,128)
    const float* w_cin = (const float*)d_in[2];   // (8,24,3,3)
    const float* b_cin = (const float*)d_in[3];   // (8,)
    const float* w_i2h = (const float*)d_in[4];   // (24,8,3,3)
    const float* b_i2h = (const float*)d_in[5];   // (24,)
    // d_in[6..12]: flow-path params + w_ret -> dead code with h0 == 0
    const float* b_ret = (const float*)d_in[13];  // (24,)
    const float* w_out = (const float*)d_in[14];  // (12,8,1,1)
    const float* b_out = (const float*)d_in[15];  // (12,)
    float* out = (float*)d_out;                   // (32,12,1,128,128)

    cudaFuncSetAttribute(convA_kernel,
                         cudaFuncAttributeMaxDynamicSharedMemorySize, A_SMEM_BYTES);
    cudaFuncSetAttribute(convB_kernel,
                         cudaFuncAttributeMaxDynamicSharedMemorySize, B_SMEM_BYTES);

    dim3 grid(128 / TX, 128 / TY, 32);            // (4,8,32) = 1024 blocks
    convA_kernel<<<grid, THREADS, A_SMEM_BYTES>>>(radar, pred, w_cin, b_cin);
    convB_kernel<<<grid, THREADS, B_SMEM_BYTES>>>(w_i2h, b_i2h, b_ret,
                                                  w_out, b_out, out);
}

// round 12
// speedup vs baseline: 1.1398x; 1.1398x over previous
#include <cuda_runtime.h>

// ---------------------------------------------------------------------------
// RadarSecondStageGenerator, fused (R5 structure, 131us baseline).
// R12: software pipelining — unroll the channel loops by 2 so ptxas can hoist
// next-iteration LDS loads above current-iteration FFMA2s (the unroll-1
// backedge was blocking all cross-iteration load prefetch).
// Arithmetic order per accumulator unchanged -> bit-identical results.
// ---------------------------------------------------------------------------

#define THREADS 256
#define TX 32
#define TY 16

// shared memory layout (in floats)
#define IN_S_OFF   0                        // [24][20][36] input tile + halo2
#define IN_S_SIZE  (24*20*36 + 8)
#define X_S_OFF    (IN_S_OFF + IN_S_SIZE)   // [8][18][36]  x tile + halo1
#define X_S_SIZE   (8*18*36)
#define WCIN_OFF   (X_S_OFF + X_S_SIZE)     // [ci=24][k=9][co=8]
#define WI2H_OFF   (WCIN_OFF + 1728)        // [ci=8][k=9][o=24]
#define WOUT_OFF   (WI2H_OFF + 1728)        // [t=12][c=8]
#define BCIN_OFF   (WOUT_OFF + 96)
#define BI2H_OFF   (BCIN_OFF + 8)
#define BRET_OFF   (BI2H_OFF + 24)
#define BOUT_OFF   (BRET_OFF + 24)
#define SMEM_FLOATS (BOUT_OFF + 12)
#define SMEM_BYTES (SMEM_FLOATS * 4)

typedef unsigned long long u64;

__device__ __forceinline__ float sigmoidf_(float x) {
    return __fdividef(1.0f, 1.0f + __expf(-x));
}

__device__ __forceinline__ u64 pk2(float lo, float hi) {
    u64 r; asm("mov.b64 %0, {%1, %2};" : "=l"(r) : "f"(lo), "f"(hi)); return r;
}
__device__ __forceinline__ u64 ffma2(u64 a, u64 b, u64 c) {
    u64 d; asm("fma.rn.f32x2 %0, %1, %2, %3;" : "=l"(d) : "l"(a), "l"(b), "l"(c)); return d;
}
__device__ __forceinline__ float2 upk2(u64 v) {
    float2 f; asm("mov.b64 {%0, %1}, %2;" : "=f"(f.x), "=f"(f.y) : "l"(v)); return f;
}

__global__ void __launch_bounds__(THREADS, 2)
radar2nd_fused_kernel(const float* __restrict__ radar,
                      const float* __restrict__ pred,
                      const float* __restrict__ w_cin,
                      const float* __restrict__ b_cin,
                      const float* __restrict__ w_i2h,
                      const float* __restrict__ b_i2h,
                      const float* __restrict__ b_ret,
                      const float* __restrict__ w_out,
                      const float* __restrict__ b_out,
                      float* __restrict__ out)
{
    extern __shared__ float sm[];
    float* in_s   = sm + IN_S_OFF;
    float* x_s    = sm + X_S_OFF;
    float* wcin_s = sm + WCIN_OFF;
    float* wi2h_s = sm + WI2H_OFF;
    float* wout_s = sm + WOUT_OFF;
    float* bcin_s = sm + BCIN_OFF;
    float* bi2h_s = sm + BI2H_OFF;
    float* bret_s = sm + BRET_OFF;
    float* bout_s = sm + BOUT_OFF;

    const int tid = threadIdx.x;
    const int b   = blockIdx.z;
    const int ty0 = blockIdx.y * TY;
    const int tx0 = blockIdx.x * TX;

    // ---------------- phase 0: stage + reorder weights into smem ----------
    // wcin_s[((ci*3+ky)*3+kx)*8 + co] = w_cin[((co*24+ci)*3+ky)*3+kx]
    for (int i = tid; i < 1728; i += THREADS) {
        int co = i & 7;
        int r  = i >> 3;
        int ci = r / 9;
        int k  = r - ci * 9;
        wcin_s[i] = w_cin[(co * 24 + ci) * 9 + k];
    }
    // wi2h_s[(ci*9 + k)*24 + o] = w_i2h[(o*8+ci)*9+k]
    for (int i = tid; i < 1728; i += THREADS) {
        int o  = i % 24;
        int r  = i / 24;
        int ci = r / 9;
        int k  = r - ci * 9;
        wi2h_s[i] = w_i2h[(o * 8 + ci) * 9 + k];
    }
    if (tid < 96) wout_s[tid] = w_out[tid];
    if (tid < 8)  bcin_s[tid] = b_cin[tid];
    if (tid < 24) bi2h_s[tid] = b_i2h[tid];
    if (tid < 24) bret_s[tid] = b_ret[tid];
    if (tid < 12) bout_s[tid] = b_out[tid];

    // ---------------- phase 1: load input tile (24ch, 20x36, zero-pad) ----
    #pragma unroll 4
    for (int i = tid; i < 24 * 20 * 36; i += THREADS) {
        int xx = i % 36;
        int r  = i / 36;
        int yy = r % 20;
        int ch = r / 20;
        int gy = ty0 + yy - 2;
        int gx = tx0 + xx - 2;
        float v = 0.0f;
        if ((unsigned)gy < 128u && (unsigned)gx < 128u) {
            const float* src = (ch < 12) ? radar : pred;
            int c = (ch < 12) ? ch : ch - 12;
            v = __ldg(&src[((b * 12 + c) << 14) + (gy << 7) + gx]);
        }
        in_s[i] = v;
    }
    __syncthreads();

    // ---------------- phase 2: x = conv3x3(24 -> 8) on 18x34 region -------
    // 3-px strips, 12 strips/row x 18 rows = 216 active threads.
    if (tid < 216) {
        const int row = tid / 12;
        const int xs  = (tid - row * 12) * 3;

        u64 acc2[4][3];                     // [co_pair][px]
        #pragma unroll
        for (int cp = 0; cp < 4; cp++) {
            u64 bv = pk2(bcin_s[2 * cp], bcin_s[2 * cp + 1]);
            #pragma unroll
            for (int px = 0; px < 3; px++) acc2[cp][px] = bv;
        }

        #pragma unroll 2
        for (int ci = 0; ci < 24; ci++) {
            #pragma unroll
            for (int dy = 0; dy < 3; dy++) {
                const float* ap = &in_s[(ci * 20 + row + dy) * 36 + xs];
                u64 ad[5];
                #pragma unroll
                for (int q = 0; q < 5; q++) { float a = ap[q]; ad[q] = pk2(a, a); }
                #pragma unroll
                for (int dx = 0; dx < 3; dx++) {
                    const u64* wp2 = (const u64*)&wcin_s[((ci * 3 + dy) * 3 + dx) * 8];
                    ulonglong2 wA = *(const ulonglong2*)(wp2);
                    ulonglong2 wB = *(const ulonglong2*)(wp2 + 2);
                    u64 wv[4] = {wA.x, wA.y, wB.x, wB.y};
                    #pragma unroll
                    for (int cp = 0; cp < 4; cp++) {
                        #pragma unroll
                        for (int px = 0; px < 3; px++)
                            acc2[cp][px] = ffma2(ad[dx + px], wv[cp], acc2[cp][px]);
                    }
                }
            }
        }

        // Store; x outside the global image is ZERO (second conv's padding).
        const int gyr = ty0 + row - 1;
        const bool rin = (unsigned)gyr < 128u;
        #pragma unroll
        for (int px = 0; px < 3; px++) {
            int c = xs + px;
            if (c < 34) {
                const int gxc = tx0 + c - 1;
                const bool inb = rin && ((unsigned)gxc < 128u);
                #pragma unroll
                for (int cp = 0; cp < 4; cp++) {
                    float2 v = upk2(acc2[cp][px]);
                    x_s[((2 * cp + 0) * 18 + row) * 36 + c] = inb ? v.x : 0.0f;
                    x_s[((2 * cp + 1) * 18 + row) * 36 + c] = inb ? v.y : 0.0f;
                }
            }
        }
    }
    __syncthreads();

    // ---------------- phase 3: i2h conv3x3(8 -> 24) + gates + conv1x1 -----
    // 2-px strips: 16 strips/row x 16 rows = all 256 threads active.
    {
        const int row = tid >> 4;          // 0..15 tile row
        const int xs  = (tid & 15) * 2;    // 0..30 tile col base

        u64 acc3[12][2];                   // [o_pair][px]
        #pragma unroll
        for (int op = 0; op < 12; op++) {
            u64 bv = pk2(bi2h_s[2 * op], bi2h_s[2 * op + 1]);
            #pragma unroll
            for (int px = 0; px < 2; px++) acc3[op][px] = bv;
        }

        #pragma unroll 2
        for (int ci = 0; ci < 8; ci++) {
            #pragma unroll
            for (int dy = 0; dy < 3; dy++) {
                const float* ap = &x_s[(ci * 18 + row + dy) * 36 + xs];
                float2 a01 = *(const float2*)ap;
                float2 a23 = *(const float2*)(ap + 2);
                u64 ad[4];
                ad[0] = pk2(a01.x, a01.x); ad[1] = pk2(a01.y, a01.y);
                ad[2] = pk2(a23.x, a23.x); ad[3] = pk2(a23.y, a23.y);
                #pragma unroll
                for (int dx = 0; dx < 3; dx++) {
                    const u64* wp2 = (const u64*)&wi2h_s[(ci * 9 + dy * 3 + dx) * 24];
                    #pragma unroll
                    for (int q = 0; q < 6; q++) {
                        ulonglong2 w2 = *(const ulonglong2*)(wp2 + q * 2);
                        #pragma unroll
                        for (int px = 0; px < 2; px++) {
                            acc3[2 * q + 0][px] = ffma2(ad[dx + px], w2.x, acc3[2 * q + 0][px]);
                            acc3[2 * q + 1][px] = ffma2(ad[dx + px], w2.y, acc3[2 * q + 1][px]);
                        }
                    }
                }
            }
        }

        // gates (h2h from h0==0 is just b_ret broadcast)
        float h[8][2];
        #pragma unroll
        for (int cp = 0; cp < 4; cp++) {
            float br0 = bret_s[2 * cp],      br1 = bret_s[2 * cp + 1];
            float bu0 = bret_s[8 + 2 * cp],  bu1 = bret_s[8 + 2 * cp + 1];
            float bm0 = bret_s[16 + 2 * cp], bm1 = bret_s[16 + 2 * cp + 1];
            #pragma unroll
            for (int px = 0; px < 2; px++) {
                float2 ir = upk2(acc3[cp][px]);
                float2 iu = upk2(acc3[4 + cp][px]);
                float2 im = upk2(acc3[8 + cp][px]);
                float rg0 = sigmoidf_(ir.x + br0);
                float rg1 = sigmoidf_(ir.y + br1);
                float ug0 = sigmoidf_(iu.x + bu0);
                float ug1 = sigmoidf_(iu.y + bu1);
                float m0 = fmaf(rg0, bm0, im.x);
                float m1 = fmaf(rg1, bm1, im.y);
                m0 = (m0 >= 0.0f) ? m0 : 0.2f * m0;
                m1 = (m1 >= 0.0f) ? m1 : 0.2f * m1;
                h[2 * cp + 0][px] = (1.0f - ug0) * m0;
                h[2 * cp + 1][px] = (1.0f - ug1) * m1;
            }
        }

        // conv1x1 (8 -> 12) + store; pack px pair for f32x2
        const int gy  = ty0 + row;
        const int gx0 = tx0 + xs;
        float* op_ = out + ((b * 12) << 14) + (gy << 7) + gx0;
        u64 hp[8];
        #pragma unroll
        for (int c = 0; c < 8; c++) hp[c] = pk2(h[c][0], h[c][1]);
        #pragma unroll
        for (int t = 0; t < 12; t++) {
            u64 o01 = pk2(bout_s[t], bout_s[t]);
            #pragma unroll
            for (int c = 0; c < 8; c++) {
                float w = wout_s[t * 8 + c];
                o01 = ffma2(hp[c], pk2(w, w), o01);
            }
            float2 a = upk2(o01);
            *(float2*)(op_ + (t << 14)) = a;
        }
    }
}

extern "C" void kernel_launch(void* const* d_in, const int* in_sizes, int n_in,
                              void* d_out, int out_size)
{
    const float* radar = (const float*)d_in[0];   // (32,12,1,128,128)
    const float* pred  = (const float*)d_in[1];   // (32,12,1,128,128)
    const float* w_cin = (const float*)d_in[2];   // (8,24,3,3)
    const float* b_cin = (const float*)d_in[3];   // (8,)
    const float* w_i2h = (const float*)d_in[4];   // (24,8,3,3)
    const float* b_i2h = (const float*)d_in[5];   // (24,)
    // d_in[6..12]: flow-path params + w_ret -> dead code with h0 == 0
    const float* b_ret = (const float*)d_in[13];  // (24,)
    const float* w_out = (const float*)d_in[14];  // (12,8,1,1)
    const float* b_out = (const float*)d_in[15];  // (12,)
    float* out = (float*)d_out;                   // (32,12,1,128,128)

    cudaFuncSetAttribute(radar2nd_fused_kernel,
                         cudaFuncAttributeMaxDynamicSharedMemorySize, SMEM_BYTES);

    dim3 grid(128 / TX, 128 / TY, 32);            // (4,8,32) = 1024 blocks
    radar2nd_fused_kernel<<<grid, THREADS, SMEM_BYTES>>>(
        radar, pred, w_cin, b_cin, w_i2h, b_i2h, b_ret, w_out, b_out, out);
}

// round 14
// speedup vs baseline: 1.1765x; 1.0321x over previous
#include <cuda_runtime.h>

// ---------------------------------------------------------------------------
// RadarSecondStageGenerator, fused, persistent. R13:
//  - 296 persistent CTAs (2/SM), each grid-strides over the 1024 tiles
//    (kills the 46%-empty 4th wave; weights staged once per CTA)
//  - input staged in 8-channel chunks via cp.async (zfill handles halo)
//    into ping-pong buffers: chunk g+1 (or next tile's chunk 0) is in
//    flight while chunk g is being consumed -> loader latency hidden.
// Compute phases identical to R12 -> bit-identical results.
// ---------------------------------------------------------------------------

#define THREADS 256
#define TX 32
#define TY 16
#define NUM_CTAS 304          // 2 per SM on GB300 (152 SMs); extras just queue
#define NTILES 1024           // 4 x 8 x 32

// shared memory layout (in floats)
#define CHUNK_FLOATS (8*20*36)              // 5760 (8ch, 20x36 halo-2 tile)
#define IN0_OFF    0
#define IN1_OFF    (IN0_OFF + CHUNK_FLOATS)
#define X_S_OFF    (IN1_OFF + CHUNK_FLOATS) // [8][18][36] x tile + halo1
#define X_S_SIZE   (8*18*36)
#define WCIN_OFF   (X_S_OFF + X_S_SIZE)     // [ci=24][k=9][co=8]
#define WI2H_OFF   (WCIN_OFF + 1728)        // [ci=8][k=9][o=24]
#define WOUT_OFF   (WI2H_OFF + 1728)        // [t=12][c=8]
#define BCIN_OFF   (WOUT_OFF + 96)
#define BI2H_OFF   (BCIN_OFF + 8)
#define BRET_OFF   (BI2H_OFF + 24)
#define BOUT_OFF   (BRET_OFF + 24)
#define SMEM_FLOATS (BOUT_OFF + 12)
#define SMEM_BYTES (SMEM_FLOATS * 4)

typedef unsigned long long u64;

__device__ __forceinline__ float sigmoidf_(float x) {
    return __fdividef(1.0f, 1.0f + __expf(-x));
}
__device__ __forceinline__ u64 pk2(float lo, float hi) {
    u64 r; asm("mov.b64 %0, {%1, %2};" : "=l"(r) : "f"(lo), "f"(hi)); return r;
}
__device__ __forceinline__ u64 ffma2(u64 a, u64 b, u64 c) {
    u64 d; asm("fma.rn.f32x2 %0, %1, %2, %3;" : "=l"(d) : "l"(a), "l"(b), "l"(c)); return d;
}
__device__ __forceinline__ float2 upk2(u64 v) {
    float2 f; asm("mov.b64 {%0, %1}, %2;" : "=f"(f.x), "=f"(f.y) : "l"(v)); return f;
}

// async-copy one 8-channel chunk (5760 x 4B) with zero-fill halo
__device__ __forceinline__ void issue_chunk(const float* __restrict__ radar,
                                            const float* __restrict__ pred,
                                            int b, int ty0, int tx0, int chbase,
                                            unsigned dst_base, int tid)
{
    #pragma unroll 1
    for (int i = tid; i < CHUNK_FLOATS; i += THREADS) {
        int xx = i % 36;
        int r  = i / 36;
        int yy = r % 20;
        int cc = r / 20;
        int ch = chbase + cc;
        int gy = ty0 + yy - 2;
        int gx = tx0 + xx - 2;
        bool v = ((unsigned)gy < 128u) && ((unsigned)gx < 128u);
        const float* src = (ch < 12)
            ? radar + (((b * 12 + ch) << 14))
            : pred  + (((b * 12 + ch - 12) << 14));
        const float* g = src + (v ? ((gy << 7) + gx) : 0);
        unsigned dst = dst_base + (unsigned)(i * 4);
        int sz = v ? 4 : 0;
        asm volatile("cp.async.ca.shared.global [%0], [%1], 4, %2;"
                     :: "r"(dst), "l"(g), "r"(sz));
    }
}

__global__ void __launch_bounds__(THREADS, 2)
radar2nd_persist_kernel(const float* __restrict__ radar,
                        const float* __restrict__ pred,
                        const float* __restrict__ w_cin,
                        const float* __restrict__ b_cin,
                        const float* __restrict__ w_i2h,
                        const float* __restrict__ b_i2h,
                        const float* __restrict__ b_ret,
                        const float* __restrict__ w_out,
                        const float* __restrict__ b_out,
                        float* __restrict__ out)
{
    extern __shared__ float sm[];
    float* x_s    = sm + X_S_OFF;
    float* wcin_s = sm + WCIN_OFF;
    float* wi2h_s = sm + WI2H_OFF;
    float* wout_s = sm + WOUT_OFF;
    float* bcin_s = sm + BCIN_OFF;
    float* bi2h_s = sm + BI2H_OFF;
    float* bret_s = sm + BRET_OFF;
    float* bout_s = sm + BOUT_OFF;

    const int tid = threadIdx.x;
    const unsigned smem_base = (unsigned)__cvta_generic_to_shared(sm);

    // ---------------- stage weights once per CTA --------------------------
    for (int i = tid; i < 1728; i += THREADS) {
        int co = i & 7;
        int r  = i >> 3;
        int ci = r / 9;
        int k  = r - ci * 9;
        wcin_s[i] = w_cin[(co * 24 + ci) * 9 + k];
    }
    for (int i = tid; i < 1728; i += THREADS) {
        int o  = i % 24;
        int r  = i / 24;
        int ci = r / 9;
        int k  = r - ci * 9;
        wi2h_s[i] = w_i2h[(o * 8 + ci) * 9 + k];
    }
    if (tid < 96) wout_s[tid] = w_out[tid];
    if (tid < 8)  bcin_s[tid] = b_cin[tid];
    if (tid < 24) bi2h_s[tid] = b_i2h[tid];
    if (tid < 24) bret_s[tid] = b_ret[tid];
    if (tid < 12) bout_s[tid] = b_out[tid];

    // prologue: async-load chunk 0 of first tile into buf 0
    {
        int t0 = blockIdx.x;
        int b0   = t0 >> 5;
        int ty00 = ((t0 >> 2) & 7) * TY;
        int tx00 = (t0 & 3) * TX;
        issue_chunk(radar, pred, b0, ty00, tx00, 0,
                    smem_base + IN0_OFF * 4, tid);
    }
    asm volatile("cp.async.commit_group;");
    __syncthreads();   // weights + biases visible before first acc init

    int cur = 0;       // ping-pong buffer holding the next chunk to consume

    // phase-2 thread map: 3-px strips, 12 strips/row x 18 rows = 216 threads
    const int p2row = tid / 12;
    const int p2xs  = (tid - p2row * 12) * 3;
    // phase-3 thread map: 2-px strips, 16 strips/row x 16 rows = 256 threads
    const int p3row = tid >> 4;
    const int p3xs  = (tid & 15) * 2;

    #pragma unroll 1
    for (int tt = blockIdx.x; tt < NTILES; tt += NUM_CTAS) {
        const int b   = tt >> 5;
        const int ty0 = ((tt >> 2) & 7) * TY;
        const int tx0 = (tt & 3) * TX;

        u64 acc2[4][3];                     // [co_pair][px]
        #pragma unroll
        for (int cp = 0; cp < 4; cp++) {
            u64 bv = pk2(bcin_s[2 * cp], bcin_s[2 * cp + 1]);
            #pragma unroll
            for (int px = 0; px < 3; px++) acc2[cp][px] = bv;
        }

        // ---------- chunked conv3x3(24->8), cp.async pipelined ------------
        #pragma unroll 1
        for (int c = 0; c < 3; c++) {
            asm volatile("cp.async.wait_group 0;");
            __syncthreads();                // chunk c data visible; buf cur^1 free

            // issue next chunk (c+1 of this tile, or chunk 0 of next tile)
            {
                int nc  = c + 1;
                int ntt = tt;
                if (nc == 3) { nc = 0; ntt = tt + NUM_CTAS; }
                if (ntt < NTILES) {
                    int nb   = ntt >> 5;
                    int nty0 = ((ntt >> 2) & 7) * TY;
                    int ntx0 = (ntt & 3) * TX;
                    unsigned dstb = smem_base +
                        (unsigned)((cur ? IN0_OFF : IN1_OFF) * 4);
                    issue_chunk(radar, pred, nb, nty0, ntx0, nc * 8, dstb, tid);
                }
            }
            asm volatile("cp.async.commit_group;");

            // accumulate this chunk
            if (tid < 216) {
                const float* in_s = sm + (cur ? IN1_OFF : IN0_OFF);
                #pragma unroll 1
                for (int cc = 0; cc < 8; cc++) {
                    const int ci = c * 8 + cc;
                    #pragma unroll
                    for (int dy = 0; dy < 3; dy++) {
                        const float* ap = &in_s[(cc * 20 + p2row + dy) * 36 + p2xs];
                        u64 ad[5];
                        #pragma unroll
                        for (int q = 0; q < 5; q++) { float a = ap[q]; ad[q] = pk2(a, a); }
                        #pragma unroll
                        for (int dx = 0; dx < 3; dx++) {
                            const u64* wp2 = (const u64*)&wcin_s[((ci * 3 + dy) * 3 + dx) * 8];
                            ulonglong2 wA = *(const ulonglong2*)(wp2);
                            ulonglong2 wB = *(const ulonglong2*)(wp2 + 2);
                            u64 wv[4] = {wA.x, wA.y, wB.x, wB.y};
                            #pragma unroll
                            for (int cp = 0; cp < 4; cp++) {
                                #pragma unroll
                                for (int px = 0; px < 3; px++)
                                    acc2[cp][px] = ffma2(ad[dx + px], wv[cp], acc2[cp][px]);
                            }
                        }
                    }
                }
            }
            cur ^= 1;
        }

        // store x; outside the global image x is ZERO (2nd conv's padding)
        if (tid < 216) {
            const int gyr = ty0 + p2row - 1;
            const bool rin = (unsigned)gyr < 128u;
            #pragma unroll
            for (int px = 0; px < 3; px++) {
                int cxl = p2xs + px;
                if (cxl < 34) {
                    const int gxc = tx0 + cxl - 1;
                    const bool inb = rin && ((unsigned)gxc < 128u);
                    #pragma unroll
                    for (int cp = 0; cp < 4; cp++) {
                        float2 v = upk2(acc2[cp][px]);
                        x_s[((2 * cp + 0) * 18 + p2row) * 36 + cxl] = inb ? v.x : 0.0f;
                        x_s[((2 * cp + 1) * 18 + p2row) * 36 + cxl] = inb ? v.y : 0.0f;
                    }
                }
            }
        }
        __syncthreads();

        // ---------- phase 3: i2h conv3x3(8->24) + gates + conv1x1 ---------
        {
            u64 acc3[12][2];                // [o_pair][px]
            #pragma unroll
            for (int op = 0; op < 12; op++) {
                u64 bv = pk2(bi2h_s[2 * op], bi2h_s[2 * op + 1]);
                acc3[op][0] = bv; acc3[op][1] = bv;
            }

            #pragma unroll 1
            for (int ci = 0; ci < 8; ci++) {
                #pragma unroll
                for (int dy = 0; dy < 3; dy++) {
                    const float* ap = &x_s[(ci * 18 + p3row + dy) * 36 + p3xs];
                    float2 a01 = *(const float2*)ap;
                    float2 a23 = *(const float2*)(ap + 2);
                    u64 ad[4];
                    ad[0] = pk2(a01.x, a01.x); ad[1] = pk2(a01.y, a01.y);
                    ad[2] = pk2(a23.x, a23.x); ad[3] = pk2(a23.y, a23.y);
                    #pragma unroll
                    for (int dx = 0; dx < 3; dx++) {
                        const u64* wp2 = (const u64*)&wi2h_s[(ci * 9 + dy * 3 + dx) * 24];
                        #pragma unroll
                        for (int q = 0; q < 6; q++) {
                            ulonglong2 w2 = *(const ulonglong2*)(wp2 + q * 2);
                            #pragma unroll
                            for (int px = 0; px < 2; px++) {
                                acc3[2 * q + 0][px] = ffma2(ad[dx + px], w2.x, acc3[2 * q + 0][px]);
                                acc3[2 * q + 1][px] = ffma2(ad[dx + px], w2.y, acc3[2 * q + 1][px]);
                            }
                        }
                    }
                }
            }

            // gates (h2h from h0==0 is just b_ret broadcast)
            float h[8][2];
            #pragma unroll
            for (int cp = 0; cp < 4; cp++) {
                float br0 = bret_s[2 * cp],      br1 = bret_s[2 * cp + 1];
                float bu0 = bret_s[8 + 2 * cp],  bu1 = bret_s[8 + 2 * cp + 1];
                float bm0 = bret_s[16 + 2 * cp], bm1 = bret_s[16 + 2 * cp + 1];
                #pragma unroll
                for (int px = 0; px < 2; px++) {
                    float2 ir = upk2(acc3[cp][px]);
                    float2 iu = upk2(acc3[4 + cp][px]);
                    float2 im = upk2(acc3[8 + cp][px]);
                    float rg0 = sigmoidf_(ir.x + br0);
                    float rg1 = sigmoidf_(ir.y + br1);
                    float ug0 = sigmoidf_(iu.x + bu0);
                    float ug1 = sigmoidf_(iu.y + bu1);
                    float m0 = fmaf(rg0, bm0, im.x);
                    float m1 = fmaf(rg1, bm1, im.y);
                    m0 = (m0 >= 0.0f) ? m0 : 0.2f * m0;
                    m1 = (m1 >= 0.0f) ? m1 : 0.2f * m1;
                    h[2 * cp + 0][px] = (1.0f - ug0) * m0;
                    h[2 * cp + 1][px] = (1.0f - ug1) * m1;
                }
            }

            // conv1x1 (8 -> 12) + store
            const int gy  = ty0 + p3row;
            const int gx0 = tx0 + p3xs;
            float* op_ = out + ((b * 12) << 14) + (gy << 7) + gx0;
            u64 hp[8];
            #pragma unroll
            for (int cch = 0; cch < 8; cch++) hp[cch] = pk2(h[cch][0], h[cch][1]);
            #pragma unroll
            for (int t = 0; t < 12; t++) {
                u64 o01 = pk2(bout_s[t], bout_s[t]);
                #pragma unroll
                for (int cch = 0; cch < 8; cch++) {
                    float w = wout_s[t * 8 + cch];
                    o01 = ffma2(hp[cch], pk2(w, w), o01);
                }
                float2 a = upk2(o01);
                *(float2*)(op_ + (t << 14)) = a;
            }
        }
        // next iteration's chunk-top wait+sync protects x_s and buffers
    }
}

extern "C" void kernel_launch(void* const* d_in, const int* in_sizes, int n_in,
                              void* d_out, int out_size)
{
    const float* radar = (const float*)d_in[0];   // (32,12,1,128,128)
    const float* pred  = (const float*)d_in[1];   // (32,12,1,128,128)
    const float* w_cin = (const float*)d_in[2];   // (8,24,3,3)
    const float* b_cin = (const float*)d_in[3];   // (8,)
    const float* w_i2h = (const float*)d_in[4];   // (24,8,3,3)
    const float* b_i2h = (const float*)d_in[5];   // (24,)
    // d_in[6..12]: flow-path params + w_ret -> dead code with h0 == 0
    const float* b_ret = (const float*)d_in[13];  // (24,)
    const float* w_out = (const float*)d_in[14];  // (12,8,1,1)
    const float* b_out = (const float*)d_in[15];  // (12,)
    float* out = (float*)d_out;                   // (32,12,1,128,128)

    cudaFuncSetAttribute(radar2nd_persist_kernel,
                         cudaFuncAttributeMaxDynamicSharedMemorySize, SMEM_BYTES);

    radar2nd_persist_kernel<<<NUM_CTAS, THREADS, SMEM_BYTES>>>(
        radar, pred, w_cin, b_cin, w_i2h, b_i2h, b_ret, w_out, b_out, out);
}

// round 15
// speedup vs baseline: 1.4524x; 1.2346x over previous
#include <cuda_runtime.h>

// ---------------------------------------------------------------------------
// RadarSecondStageGenerator, fused, persistent (R13 structure, 127.5us).
// R15: adds-only cp.async loader — 2D thread map computed once, chunk index
// templated so channel->buffer selection is compile-time, per-copy address
// math is one add. Compute phases identical to R13 -> bit-identical results.
// ---------------------------------------------------------------------------

#define THREADS 256
#define TX 32
#define TY 16
#define NUM_CTAS 304          // 2 per SM on GB300 (152 SMs)
#define NTILES 1024           // 4 x 8 x 32

// shared memory layout (in floats)
#define CHUNK_FLOATS (8*20*36)              // 5760 (8ch, 20x36 halo-2 tile)
#define IN0_OFF    0
#define IN1_OFF    (IN0_OFF + CHUNK_FLOATS)
#define X_S_OFF    (IN1_OFF + CHUNK_FLOATS) // [8][18][36] x tile + halo1
#define X_S_SIZE   (8*18*36)
#define WCIN_OFF   (X_S_OFF + X_S_SIZE)     // [ci=24][k=9][co=8]
#define WI2H_OFF   (WCIN_OFF + 1728)        // [ci=8][k=9][o=24]
#define WOUT_OFF   (WI2H_OFF + 1728)        // [t=12][c=8]
#define BCIN_OFF   (WOUT_OFF + 96)
#define BI2H_OFF   (BCIN_OFF + 8)
#define BRET_OFF   (BI2H_OFF + 24)
#define BOUT_OFF   (BRET_OFF + 24)
#define SMEM_FLOATS (BOUT_OFF + 12)
#define SMEM_BYTES (SMEM_FLOATS * 4)

typedef unsigned long long u64;

__device__ __forceinline__ float sigmoidf_(float x) {
    return __fdividef(1.0f, 1.0f + __expf(-x));
}
__device__ __forceinline__ u64 pk2(float lo, float hi) {
    u64 r; asm("mov.b64 %0, {%1, %2};" : "=l"(r) : "f"(lo), "f"(hi)); return r;
}
__device__ __forceinline__ u64 ffma2(u64 a, u64 b, u64 c) {
    u64 d; asm("fma.rn.f32x2 %0, %1, %2, %3;" : "=l"(d) : "l"(a), "l"(b), "l"(c)); return d;
}
__device__ __forceinline__ float2 upk2(u64 v) {
    float2 f; asm("mov.b64 {%0, %1}, %2;" : "=f"(f.x), "=f"(f.y) : "l"(v)); return f;
}

// adds-only async chunk loader. CHUNK selects channels [CHUNK*8, CHUNK*8+8)
// at compile time (radar vs pred split resolved statically).
template<int CHUNK>
__device__ __forceinline__ void issue_chunk2(const float* __restrict__ radar,
                                             const float* __restrict__ pred,
                                             int b, int ty0, int gx, bool vx,
                                             int lty, unsigned dstb)
{
    if (lty < 7) {
        const float* bases[8];
        #pragma unroll
        for (int cc = 0; cc < 8; cc++) {
            constexpr int dummy = 0; (void)dummy;
            int ch = CHUNK * 8 + cc;
            bases[cc] = (ch < 12) ? radar + ((b * 12 + ch) << 14)
                                  : pred  + ((b * 12 + ch - 12) << 14);
        }
        #pragma unroll
        for (int k = 0; k < 3; k++) {
            const int yy = lty + 7 * k;
            if (yy < 20) {
                const int gy = ty0 + yy - 2;
                const bool v = vx && ((unsigned)gy < 128u);
                const int off = v ? ((gy << 7) + gx) : 0;
                const int sz = v ? 4 : 0;
                const unsigned dst = dstb + (unsigned)(yy * 144);
                #pragma unroll
                for (int cc = 0; cc < 8; cc++) {
                    asm volatile("cp.async.ca.shared.global [%0], [%1], 4, %2;"
                                 :: "r"(dst + (unsigned)(cc * 2880)),
                                    "l"(bases[cc] + off), "r"(sz));
                }
            }
        }
    }
}

__device__ __forceinline__ void issue_chunk_n(int nc,
                                              const float* __restrict__ radar,
                                              const float* __restrict__ pred,
                                              int b, int ty0, int gx, bool vx,
                                              int lty, unsigned dstb)
{
    if (nc == 0)      issue_chunk2<0>(radar, pred, b, ty0, gx, vx, lty, dstb);
    else if (nc == 1) issue_chunk2<1>(radar, pred, b, ty0, gx, vx, lty, dstb);
    else              issue_chunk2<2>(radar, pred, b, ty0, gx, vx, lty, dstb);
}

__global__ void __launch_bounds__(THREADS, 2)
radar2nd_persist_kernel(const float* __restrict__ radar,
                        const float* __restrict__ pred,
                        const float* __restrict__ w_cin,
                        const float* __restrict__ b_cin,
                        const float* __restrict__ w_i2h,
                        const float* __restrict__ b_i2h,
                        const float* __restrict__ b_ret,
                        const float* __restrict__ w_out,
                        const float* __restrict__ b_out,
                        float* __restrict__ out)
{
    extern __shared__ float sm[];
    float* x_s    = sm + X_S_OFF;
    float* wcin_s = sm + WCIN_OFF;
    float* wi2h_s = sm + WI2H_OFF;
    float* wout_s = sm + WOUT_OFF;
    float* bcin_s = sm + BCIN_OFF;
    float* bi2h_s = sm + BI2H_OFF;
    float* bret_s = sm + BRET_OFF;
    float* bout_s = sm + BOUT_OFF;

    const int tid = threadIdx.x;
    const unsigned smem_base = (unsigned)__cvta_generic_to_shared(sm);

    // loader 2D map (computed once)
    const int ltx = tid % 36;
    const int lty = tid / 36;                 // 0..7; lty==7 -> loader-idle
    const unsigned dst_col = smem_base + (unsigned)(ltx * 4);

    // ---------------- stage weights once per CTA --------------------------
    for (int i = tid; i < 1728; i += THREADS) {
        int co = i & 7;
        int r  = i >> 3;
        int ci = r / 9;
        int k  = r - ci * 9;
        wcin_s[i] = w_cin[(co * 24 + ci) * 9 + k];
    }
    for (int i = tid; i < 1728; i += THREADS) {
        int o  = i % 24;
        int r  = i / 24;
        int ci = r / 9;
        int k  = r - ci * 9;
        wi2h_s[i] = w_i2h[(o * 8 + ci) * 9 + k];
    }
    if (tid < 96) wout_s[tid] = w_out[tid];
    if (tid < 8)  bcin_s[tid] = b_cin[tid];
    if (tid < 24) bi2h_s[tid] = b_i2h[tid];
    if (tid < 24) bret_s[tid] = b_ret[tid];
    if (tid < 12) bout_s[tid] = b_out[tid];

    // prologue: async-load chunk 0 of first tile into buf 0
    {
        int t0 = blockIdx.x;
        int b0   = t0 >> 5;
        int ty00 = ((t0 >> 2) & 7) * TY;
        int tx00 = (t0 & 3) * TX;
        int gx0  = tx00 + ltx - 2;
        issue_chunk2<0>(radar, pred, b0, ty00, gx0, (unsigned)gx0 < 128u,
                        lty, dst_col + IN0_OFF * 4);
    }
    asm volatile("cp.async.commit_group;");
    __syncthreads();   // weights + biases visible before first acc init

    int cur = 0;       // ping-pong buffer holding the next chunk to consume

    // phase-2 thread map: 3-px strips, 12 strips/row x 18 rows = 216 threads
    const int p2row = tid / 12;
    const int p2xs  = (tid - p2row * 12) * 3;
    // phase-3 thread map: 2-px strips, 16 strips/row x 16 rows = 256 threads
    const int p3row = tid >> 4;
    const int p3xs  = (tid & 15) * 2;

    #pragma unroll 1
    for (int tt = blockIdx.x; tt < NTILES; tt += NUM_CTAS) {
        const int b   = tt >> 5;
        const int ty0 = ((tt >> 2) & 7) * TY;
        const int tx0 = (tt & 3) * TX;

        u64 acc2[4][3];                     // [co_pair][px]
        #pragma unroll
        for (int cp = 0; cp < 4; cp++) {
            u64 bv = pk2(bcin_s[2 * cp], bcin_s[2 * cp + 1]);
            #pragma unroll
            for (int px = 0; px < 3; px++) acc2[cp][px] = bv;
        }

        // ---------- chunked conv3x3(24->8), cp.async pipelined ------------
        #pragma unroll 1
        for (int c = 0; c < 3; c++) {
            asm volatile("cp.async.wait_group 0;");
            __syncthreads();                // chunk c data visible; buf cur^1 free

            // issue next chunk (c+1 of this tile, or chunk 0 of next tile)
            {
                int nc  = c + 1;
                int ntt = tt;
                if (nc == 3) { nc = 0; ntt = tt + NUM_CTAS; }
                if (ntt < NTILES) {
                    int nb   = ntt >> 5;
                    int nty0 = ((ntt >> 2) & 7) * TY;
                    int ntx0 = (ntt & 3) * TX;
                    int ngx  = ntx0 + ltx - 2;
                    unsigned dstb = dst_col +
                        (unsigned)((cur ? IN0_OFF : IN1_OFF) * 4);
                    issue_chunk_n(nc, radar, pred, nb, nty0, ngx,
                                  (unsigned)ngx < 128u, lty, dstb);
                }
            }
            asm volatile("cp.async.commit_group;");

            // accumulate this chunk
            if (tid < 216) {
                const float* in_s = sm + (cur ? IN1_OFF : IN0_OFF);
                #pragma unroll 1
                for (int cc = 0; cc < 8; cc++) {
                    const int ci = c * 8 + cc;
                    #pragma unroll
                    for (int dy = 0; dy < 3; dy++) {
                        const float* ap = &in_s[(cc * 20 + p2row + dy) * 36 + p2xs];
                        u64 ad[5];
                        #pragma unroll
                        for (int q = 0; q < 5; q++) { float a = ap[q]; ad[q] = pk2(a, a); }
                        #pragma unroll
                        for (int dx = 0; dx < 3; dx++) {
                            const u64* wp2 = (const u64*)&wcin_s[((ci * 3 + dy) * 3 + dx) * 8];
                            ulonglong2 wA = *(const ulonglong2*)(wp2);
                            ulonglong2 wB = *(const ulonglong2*)(wp2 + 2);
                            u64 wv[4] = {wA.x, wA.y, wB.x, wB.y};
                            #pragma unroll
                            for (int cp = 0; cp < 4; cp++) {
                                #pragma unroll
                                for (int px = 0; px < 3; px++)
                                    acc2[cp][px] = ffma2(ad[dx + px], wv[cp], acc2[cp][px]);
                            }
                        }
                    }
                }
            }
            cur ^= 1;
        }

        // store x; outside the global image x is ZERO (2nd conv's padding)
        if (tid < 216) {
            const int gyr = ty0 + p2row - 1;
            const bool rin = (unsigned)gyr < 128u;
            #pragma unroll
            for (int px = 0; px < 3; px++) {
                int cxl = p2xs + px;
                if (cxl < 34) {
                    const int gxc = tx0 + cxl - 1;
                    const bool inb = rin && ((unsigned)gxc < 128u);
                    #pragma unroll
                    for (int cp = 0; cp < 4; cp++) {
                        float2 v = upk2(acc2[cp][px]);
                        x_s[((2 * cp + 0) * 18 + p2row) * 36 + cxl] = inb ? v.x : 0.0f;
                        x_s[((2 * cp + 1) * 18 + p2row) * 36 + cxl] = inb ? v.y : 0.0f;
                    }
                }
            }
        }
        __syncthreads();

        // ---------- phase 3: i2h conv3x3(8->24) + gates + conv1x1 ---------
        {
            u64 acc3[12][2];                // [o_pair][px]
            #pragma unroll
            for (int op = 0; op < 12; op++) {
                u64 bv = pk2(bi2h_s[2 * op], bi2h_s[2 * op + 1]);
                acc3[op][0] = bv; acc3[op][1] = bv;
            }

            #pragma unroll 1
            for (int ci = 0; ci < 8; ci++) {
                #pragma unroll
                for (int dy = 0; dy < 3; dy++) {
                    const float* ap = &x_s[(ci * 18 + p3row + dy) * 36 + p3xs];
                    float2 a01 = *(const float2*)ap;
                    float2 a23 = *(const float2*)(ap + 2);
                    u64 ad[4];
                    ad[0] = pk2(a01.x, a01.x); ad[1] = pk2(a01.y, a01.y);
                    ad[2] = pk2(a23.x, a23.x); ad[3] = pk2(a23.y, a23.y);
                    #pragma unroll
                    for (int dx = 0; dx < 3; dx++) {
                        const u64* wp2 = (const u64*)&wi2h_s[(ci * 9 + dy * 3 + dx) * 24];
                        #pragma unroll
                        for (int q = 0; q < 6; q++) {
                            ulonglong2 w2 = *(const ulonglong2*)(wp2 + q * 2);
                            #pragma unroll
                            for (int px = 0; px < 2; px++) {
                                acc3[2 * q + 0][px] = ffma2(ad[dx + px], w2.x, acc3[2 * q + 0][px]);
                                acc3[2 * q + 1][px] = ffma2(ad[dx + px], w2.y, acc3[2 * q + 1][px]);
                            }
                        }
                    }
                }
            }

            // gates (h2h from h0==0 is just b_ret broadcast)
            float h[8][2];
            #pragma unroll
            for (int cp = 0; cp < 4; cp++) {
                float br0 = bret_s[2 * cp],      br1 = bret_s[2 * cp + 1];
                float bu0 = bret_s[8 + 2 * cp],  bu1 = bret_s[8 + 2 * cp + 1];
                float bm0 = bret_s[16 + 2 * cp], bm1 = bret_s[16 + 2 * cp + 1];
                #pragma unroll
                for (int px = 0; px < 2; px++) {
                    float2 ir = upk2(acc3[cp][px]);
                    float2 iu = upk2(acc3[4 + cp][px]);
                    float2 im = upk2(acc3[8 + cp][px]);
                    float rg0 = sigmoidf_(ir.x + br0);
                    float rg1 = sigmoidf_(ir.y + br1);
                    float ug0 = sigmoidf_(iu.x + bu0);
                    float ug1 = sigmoidf_(iu.y + bu1);
                    float m0 = fmaf(rg0, bm0, im.x);
                    float m1 = fmaf(rg1, bm1, im.y);
                    m0 = (m0 >= 0.0f) ? m0 : 0.2f * m0;
                    m1 = (m1 >= 0.0f) ? m1 : 0.2f * m1;
                    h[2 * cp + 0][px] = (1.0f - ug0) * m0;
                    h[2 * cp + 1][px] = (1.0f - ug1) * m1;
                }
            }

            // conv1x1 (8 -> 12) + store
            const int gy  = ty0 + p3row;
            const int gx0 = tx0 + p3xs;
            float* op_ = out + ((b * 12) << 14) + (gy << 7) + gx0;
            u64 hp[8];
            #pragma unroll
            for (int cch = 0; cch < 8; cch++) hp[cch] = pk2(h[cch][0], h[cch][1]);
            #pragma unroll
            for (int t = 0; t < 12; t++) {
                u64 o01 = pk2(bout_s[t], bout_s[t]);
                #pragma unroll
                for (int cch = 0; cch < 8; cch++) {
                    float w = wout_s[t * 8 + cch];
                    o01 = ffma2(hp[cch], pk2(w, w), o01);
                }
                float2 a = upk2(o01);
                *(float2*)(op_ + (t << 14)) = a;
            }
        }
        // next iteration's chunk-top wait+sync protects x_s and buffers
    }
}

extern "C" void kernel_launch(void* const* d_in, const int* in_sizes, int n_in,
                              void* d_out, int out_size)
{
    const float* radar = (const float*)d_in[0];   // (32,12,1,128,128)
    const float* pred  = (const float*)d_in[1];   // (32,12,1,128,128)
    const float* w_cin = (const float*)d_in[2];   // (8,24,3,3)
    const float* b_cin = (const float*)d_in[3];   // (8,)
    const float* w_i2h = (const float*)d_in[4];   // (24,8,3,3)
    const float* b_i2h = (const float*)d_in[5];   // (24,)
    // d_in[6..12]: flow-path params + w_ret -> dead code with h0 == 0
    const float* b_ret = (const float*)d_in[13];  // (24,)
    const float* w_out = (const float*)d_in[14];  // (12,8,1,1)
    const float* b_out = (const float*)d_in[15];  // (12,)
    float* out = (float*)d_out;                   // (32,12,1,128,128)

    cudaFuncSetAttribute(radar2nd_persist_kernel,
                         cudaFuncAttributeMaxDynamicSharedMemorySize, SMEM_BYTES);

    radar2nd_persist_kernel<<<NUM_CTAS, THREADS, SMEM_BYTES>>>(
        radar, pred, w_cin, b_cin, w_i2h, b_i2h, b_ret, w_out, b_out, out);
}

// round 16
// speedup vs baseline: 1.5464x; 1.0647x over previous
#include <cuda_runtime.h>

// ---------------------------------------------------------------------------
// RadarSecondStageGenerator, fused, persistent (R15 base, 103.3us).
// R16: dynamic tile scheduling — global atomic ticket replaces the static
// grid-stride (static split gave 112 CTAs 4 tiles vs 192 with 3 -> 19% tail).
// Next ticket fetched one tile ahead so cp.async prefetch is unchanged.
// Compute phases identical to R15 -> bit-identical results.
// ---------------------------------------------------------------------------

#define THREADS 256
#define TX 32
#define TY 16
#define NUM_CTAS 304          // 2 per SM on GB300 (152 SMs)
#define NTILES 1024           // 4 x 8 x 32

// shared memory layout (in floats)
#define CHUNK_FLOATS (8*20*36)              // 5760 (8ch, 20x36 halo-2 tile)
#define IN0_OFF    0
#define IN1_OFF    (IN0_OFF + CHUNK_FLOATS)
#define X_S_OFF    (IN1_OFF + CHUNK_FLOATS) // [8][18][36] x tile + halo1
#define X_S_SIZE   (8*18*36)
#define WCIN_OFF   (X_S_OFF + X_S_SIZE)     // [ci=24][k=9][co=8]
#define WI2H_OFF   (WCIN_OFF + 1728)        // [ci=8][k=9][o=24]
#define WOUT_OFF   (WI2H_OFF + 1728)        // [t=12][c=8]
#define BCIN_OFF   (WOUT_OFF + 96)
#define BI2H_OFF   (BCIN_OFF + 8)
#define BRET_OFF   (BI2H_OFF + 24)
#define BOUT_OFF   (BRET_OFF + 24)
#define TT_OFF     (BOUT_OFF + 12)          // next-ticket broadcast slot
#define SMEM_FLOATS (TT_OFF + 1)
#define SMEM_BYTES (SMEM_FLOATS * 4)

typedef unsigned long long u64;

__device__ unsigned g_ticket;

__device__ __forceinline__ float sigmoidf_(float x) {
    return __fdividef(1.0f, 1.0f + __expf(-x));
}
__device__ __forceinline__ u64 pk2(float lo, float hi) {
    u64 r; asm("mov.b64 %0, {%1, %2};" : "=l"(r) : "f"(lo), "f"(hi)); return r;
}
__device__ __forceinline__ u64 ffma2(u64 a, u64 b, u64 c) {
    u64 d; asm("fma.rn.f32x2 %0, %1, %2, %3;" : "=l"(d) : "l"(a), "l"(b), "l"(c)); return d;
}
__device__ __forceinline__ float2 upk2(u64 v) {
    float2 f; asm("mov.b64 {%0, %1}, %2;" : "=f"(f.x), "=f"(f.y) : "l"(v)); return f;
}

// adds-only async chunk loader. CHUNK selects channels [CHUNK*8, CHUNK*8+8)
// at compile time (radar vs pred split resolved statically).
template<int CHUNK>
__device__ __forceinline__ void issue_chunk2(const float* __restrict__ radar,
                                             const float* __restrict__ pred,
                                             int b, int ty0, int gx, bool vx,
                                             int lty, unsigned dstb)
{
    if (lty < 7) {
        const float* bases[8];
        #pragma unroll
        for (int cc = 0; cc < 8; cc++) {
            int ch = CHUNK * 8 + cc;
            bases[cc] = (ch < 12) ? radar + ((b * 12 + ch) << 14)
                                  : pred  + ((b * 12 + ch - 12) << 14);
        }
        #pragma unroll
        for (int k = 0; k < 3; k++) {
            const int yy = lty + 7 * k;
            if (yy < 20) {
                const int gy = ty0 + yy - 2;
                const bool v = vx && ((unsigned)gy < 128u);
                const int off = v ? ((gy << 7) + gx) : 0;
                const int sz = v ? 4 : 0;
                const unsigned dst = dstb + (unsigned)(yy * 144);
                #pragma unroll
                for (int cc = 0; cc < 8; cc++) {
                    asm volatile("cp.async.ca.shared.global [%0], [%1], 4, %2;"
                                 :: "r"(dst + (unsigned)(cc * 2880)),
                                    "l"(bases[cc] + off), "r"(sz));
                }
            }
        }
    }
}

__global__ void reset_ticket_kernel() { g_ticket = 0u; }

__global__ void __launch_bounds__(THREADS, 2)
radar2nd_persist_kernel(const float* __restrict__ radar,
                        const float* __restrict__ pred,
                        const float* __restrict__ w_cin,
                        const float* __restrict__ b_cin,
                        const float* __restrict__ w_i2h,
                        const float* __restrict__ b_i2h,
                        const float* __restrict__ b_ret,
                        const float* __restrict__ w_out,
                        const float* __restrict__ b_out,
                        float* __restrict__ out)
{
    extern __shared__ float sm[];
    float* x_s    = sm + X_S_OFF;
    float* wcin_s = sm + WCIN_OFF;
    float* wi2h_s = sm + WI2H_OFF;
    float* wout_s = sm + WOUT_OFF;
    float* bcin_s = sm + BCIN_OFF;
    float* bi2h_s = sm + BI2H_OFF;
    float* bret_s = sm + BRET_OFF;
    float* bout_s = sm + BOUT_OFF;
    unsigned* tt_s = (unsigned*)(sm + TT_OFF);

    const int tid = threadIdx.x;
    const unsigned smem_base = (unsigned)__cvta_generic_to_shared(sm);

    // loader 2D map (computed once)
    const int ltx = tid % 36;
    const int lty = tid / 36;                 // 0..7; lty==7 -> loader-idle
    const unsigned dst_col = smem_base + (unsigned)(ltx * 4);

    // ---------------- stage weights once per CTA --------------------------
    for (int i = tid; i < 1728; i += THREADS) {
        int co = i & 7;
        int r  = i >> 3;
        int ci = r / 9;
        int k  = r - ci * 9;
        wcin_s[i] = w_cin[(co * 24 + ci) * 9 + k];
    }
    for (int i = tid; i < 1728; i += THREADS) {
        int o  = i % 24;
        int r  = i / 24;
        int ci = r / 9;
        int k  = r - ci * 9;
        wi2h_s[i] = w_i2h[(o * 8 + ci) * 9 + k];
    }
    if (tid < 96) wout_s[tid] = w_out[tid];
    if (tid < 8)  bcin_s[tid] = b_cin[tid];
    if (tid < 24) bi2h_s[tid] = b_i2h[tid];
    if (tid < 24) bret_s[tid] = b_ret[tid];
    if (tid < 12) bout_s[tid] = b_out[tid];

    // first ticket
    if (tid == 0) tt_s[0] = atomicAdd(&g_ticket, 1u);
    __syncthreads();   // weights + biases + first ticket visible
    int tt = (int)tt_s[0];

    // prologue: async-load chunk 0 of first tile into buf 0
    if (tt < NTILES) {
        int b0   = tt >> 5;
        int ty00 = ((tt >> 2) & 7) * TY;
        int tx00 = (tt & 3) * TX;
        int gx0  = tx00 + ltx - 2;
        issue_chunk2<0>(radar, pred, b0, ty00, gx0, (unsigned)gx0 < 128u,
                        lty, dst_col + IN0_OFF * 4);
    }
    asm volatile("cp.async.commit_group;");

    int cur = 0;       // ping-pong buffer holding the next chunk to consume

    // phase-2 thread map: 3-px strips, 12 strips/row x 18 rows = 216 threads
    const int p2row = tid / 12;
    const int p2xs  = (tid - p2row * 12) * 3;
    // phase-3 thread map: 2-px strips, 16 strips/row x 16 rows = 256 threads
    const int p3row = tid >> 4;
    const int p3xs  = (tid & 15) * 2;

    #pragma unroll 1
    while (tt < NTILES) {
        const int b   = tt >> 5;
        const int ty0 = ((tt >> 2) & 7) * TY;
        const int tx0 = (tt & 3) * TX;

        // fetch next ticket early (visible by the c==2 sync below)
        if (tid == 0) tt_s[0] = atomicAdd(&g_ticket, 1u);

        u64 acc2[4][3];                     // [co_pair][px]
        #pragma unroll
        for (int cp = 0; cp < 4; cp++) {
            u64 bv = pk2(bcin_s[2 * cp], bcin_s[2 * cp + 1]);
            #pragma unroll
            for (int px = 0; px < 3; px++) acc2[cp][px] = bv;
        }

        int ntt = NTILES;                   // next tile (read at c==2)

        // ---------- chunked conv3x3(24->8), cp.async pipelined ------------
        #pragma unroll 1
        for (int c = 0; c < 3; c++) {
            asm volatile("cp.async.wait_group 0;");
            __syncthreads();                // chunk c data visible; buf cur^1 free

            // issue next chunk (c+1 of this tile, or chunk 0 of next tile)
            {
                unsigned dstb = dst_col +
                    (unsigned)((cur ? IN0_OFF : IN1_OFF) * 4);
                if (c == 0) {
                    int gx = tx0 + ltx - 2;
                    issue_chunk2<1>(radar, pred, b, ty0, gx,
                                    (unsigned)gx < 128u, lty, dstb);
                } else if (c == 1) {
                    int gx = tx0 + ltx - 2;
                    issue_chunk2<2>(radar, pred, b, ty0, gx,
                                    (unsigned)gx < 128u, lty, dstb);
                } else {
                    ntt = (int)tt_s[0];     // made visible by this chunk's sync
                    if (ntt < NTILES) {
                        int nb   = ntt >> 5;
                        int nty0 = ((ntt >> 2) & 7) * TY;
                        int ntx0 = (ntt & 3) * TX;
                        int ngx  = ntx0 + ltx - 2;
                        issue_chunk2<0>(radar, pred, nb, nty0, ngx,
                                        (unsigned)ngx < 128u, lty, dstb);
                    }
                }
            }
            asm volatile("cp.async.commit_group;");

            // accumulate this chunk
            if (tid < 216) {
                const float* in_s = sm + (cur ? IN1_OFF : IN0_OFF);
                #pragma unroll 1
                for (int cc = 0; cc < 8; cc++) {
                    const int ci = c * 8 + cc;
                    #pragma unroll
                    for (int dy = 0; dy < 3; dy++) {
                        const float* ap = &in_s[(cc * 20 + p2row + dy) * 36 + p2xs];
                        u64 ad[5];
                        #pragma unroll
                        for (int q = 0; q < 5; q++) { float a = ap[q]; ad[q] = pk2(a, a); }
                        #pragma unroll
                        for (int dx = 0; dx < 3; dx++) {
                            const u64* wp2 = (const u64*)&wcin_s[((ci * 3 + dy) * 3 + dx) * 8];
                            ulonglong2 wA = *(const ulonglong2*)(wp2);
                            ulonglong2 wB = *(const ulonglong2*)(wp2 + 2);
                            u64 wv[4] = {wA.x, wA.y, wB.x, wB.y};
                            #pragma unroll
                            for (int cp = 0; cp < 4; cp++) {
                                #pragma unroll
                                for (int px = 0; px < 3; px++)
                                    acc2[cp][px] = ffma2(ad[dx + px], wv[cp], acc2[cp][px]);
                            }
                        }
                    }
                }
            }
            cur ^= 1;
        }

        // store x; outside the global image x is ZERO (2nd conv's padding)
        if (tid < 216) {
            const int gyr = ty0 + p2row - 1;
            const bool rin = (unsigned)gyr < 128u;
            #pragma unroll
            for (int px = 0; px < 3; px++) {
                int cxl = p2xs + px;
                if (cxl < 34) {
                    const int gxc = tx0 + cxl - 1;
                    const bool inb = rin && ((unsigned)gxc < 128u);
                    #pragma unroll
                    for (int cp = 0; cp < 4; cp++) {
                        float2 v = upk2(acc2[cp][px]);
                        x_s[((2 * cp + 0) * 18 + p2row) * 36 + cxl] = inb ? v.x : 0.0f;
                        x_s[((2 * cp + 1) * 18 + p2row) * 36 + cxl] = inb ? v.y : 0.0f;
                    }
                }
            }
        }
        __syncthreads();

        // ---------- phase 3: i2h conv3x3(8->24) + gates + conv1x1 ---------
        {
            u64 acc3[12][2];                // [o_pair][px]
            #pragma unroll
            for (int op = 0; op < 12; op++) {
                u64 bv = pk2(bi2h_s[2 * op], bi2h_s[2 * op + 1]);
                acc3[op][0] = bv; acc3[op][1] = bv;
            }

            #pragma unroll 1
            for (int ci = 0; ci < 8; ci++) {
                #pragma unroll
                for (int dy = 0; dy < 3; dy++) {
                    const float* ap = &x_s[(ci * 18 + p3row + dy) * 36 + p3xs];
                    float2 a01 = *(const float2*)ap;
                    float2 a23 = *(const float2*)(ap + 2);
                    u64 ad[4];
                    ad[0] = pk2(a01.x, a01.x); ad[1] = pk2(a01.y, a01.y);
                    ad[2] = pk2(a23.x, a23.x); ad[3] = pk2(a23.y, a23.y);
                    #pragma unroll
                    for (int dx = 0; dx < 3; dx++) {
                        const u64* wp2 = (const u64*)&wi2h_s[(ci * 9 + dy * 3 + dx) * 24];
                        #pragma unroll
                        for (int q = 0; q < 6; q++) {
                            ulonglong2 w2 = *(const ulonglong2*)(wp2 + q * 2);
                            #pragma unroll
                            for (int px = 0; px < 2; px++) {
                                acc3[2 * q + 0][px] = ffma2(ad[dx + px], w2.x, acc3[2 * q + 0][px]);
                                acc3[2 * q + 1][px] = ffma2(ad[dx + px], w2.y, acc3[2 * q + 1][px]);
                            }
                        }
                    }
                }
            }

            // gates (h2h from h0==0 is just b_ret broadcast)
            float h[8][2];
            #pragma unroll
            for (int cp = 0; cp < 4; cp++) {
                float br0 = bret_s[2 * cp],      br1 = bret_s[2 * cp + 1];
                float bu0 = bret_s[8 + 2 * cp],  bu1 = bret_s[8 + 2 * cp + 1];
                float bm0 = bret_s[16 + 2 * cp], bm1 = bret_s[16 + 2 * cp + 1];
                #pragma unroll
                for (int px = 0; px < 2; px++) {
                    float2 ir = upk2(acc3[cp][px]);
                    float2 iu = upk2(acc3[4 + cp][px]);
                    float2 im = upk2(acc3[8 + cp][px]);
                    float rg0 = sigmoidf_(ir.x + br0);
                    float rg1 = sigmoidf_(ir.y + br1);
                    float ug0 = sigmoidf_(iu.x + bu0);
                    float ug1 = sigmoidf_(iu.y + bu1);
                    float m0 = fmaf(rg0, bm0, im.x);
                    float m1 = fmaf(rg1, bm1, im.y);
                    m0 = (m0 >= 0.0f) ? m0 : 0.2f * m0;
                    m1 = (m1 >= 0.0f) ? m1 : 0.2f * m1;
                    h[2 * cp + 0][px] = (1.0f - ug0) * m0;
                    h[2 * cp + 1][px] = (1.0f - ug1) * m1;
                }
            }

            // conv1x1 (8 -> 12) + store
            const int gy  = ty0 + p3row;
            const int gx0 = tx0 + p3xs;
            float* op_ = out + ((b * 12) << 14) + (gy << 7) + gx0;
            u64 hp[8];
            #pragma unroll
            for (int cch = 0; cch < 8; cch++) hp[cch] = pk2(h[cch][0], h[cch][1]);
            #pragma unroll
            for (int t = 0; t < 12; t++) {
                u64 o01 = pk2(bout_s[t], bout_s[t]);
                #pragma unroll
                for (int cch = 0; cch < 8; cch++) {
                    float w = wout_s[t * 8 + cch];
                    o01 = ffma2(hp[cch], pk2(w, w), o01);
                }
                float2 a = upk2(o01);
                *(float2*)(op_ + (t << 14)) = a;
            }
        }

        tt = ntt;
        // next iteration's chunk-top wait+sync protects x_s and buffers
    }
}

extern "C" void kernel_launch(void* const* d_in, const int* in_sizes, int n_in,
                              void* d_out, int out_size)
{
    const float* radar = (const float*)d_in[0];   // (32,12,1,128,128)
    const float* pred  = (const float*)d_in[1];   // (32,12,1,128,128)
    const float* w_cin = (const float*)d_in[2];   // (8,24,3,3)
    const float* b_cin = (const float*)d_in[3];   // (8,)
    const float* w_i2h = (const float*)d_in[4];   // (24,8,3,3)
    const float* b_i2h = (const float*)d_in[5];   // (24,)
    // d_in[6..12]: flow-path params + w_ret -> dead code with h0 == 0
    const float* b_ret = (const float*)d_in[13];  // (24,)
    const float* w_out = (const float*)d_in[14];  // (12,8,1,1)
    const float* b_out = (const float*)d_in[15];  // (12,)
    float* out = (float*)d_out;                   // (32,12,1,128,128)

    cudaFuncSetAttribute(radar2nd_persist_kernel,
                         cudaFuncAttributeMaxDynamicSharedMemorySize, SMEM_BYTES);

    reset_ticket_kernel<<<1, 1>>>();
    radar2nd_persist_kernel<<<NUM_CTAS, THREADS, SMEM_BYTES>>>(
        radar, pred, w_cin, b_cin, w_i2h, b_i2h, b_ret, w_out, b_out, out);
}